// round 4
// baseline (speedup 1.0000x reference)
#include <cuda_runtime.h>
#include <cuda_bf16.h>

#define T 256
#define Bt 64
#define EMB 300
#define HID 256
#define G4 1024
#define NLAB 20

// ---------------- scratch (static device allocations are the sanctioned path) ----
__device__ float g_xproj[2][T][G4][Bt];   // [dir][t][gate][batch]  ~134MB
__device__ float g_h[2][T][HID][Bt];      // [dir][t][hid][batch]   ~33.5MB
__device__ float g_em[T][Bt][NLAB];       // emissions
__device__ float g_part[Bt];              // per-batch nll parts
__device__ unsigned g_bar[2];             // [0]=count, [1]=release

// =============================================================================
// Kernel 1: x_proj = emb[sent] @ Wih^T + b  for both directions.
// GEMM M=16384 (one t per M-tile of 64), N=2048 (f gates then b gates), K=300.
// 64x64 tile, 256 threads, 4x4 microtile.
// =============================================================================
__global__ void __launch_bounds__(256) k_xproj(
    const float* __restrict__ emb,
    const float* __restrict__ Wf, const float* __restrict__ bf,
    const float* __restrict__ Wb, const float* __restrict__ bb,
    const int*   __restrict__ sent)
{
    __shared__ float As[32*68];   // [k][m], padded
    __shared__ float Bs[32*68];   // [k][n], padded
    __shared__ int   ws[64];

    int t   = blockIdx.y;
    int n0  = blockIdx.x * 64;
    int dir = (n0 >= 1024) ? 1 : 0;
    const float* W    = dir ? Wb : Wf;
    const float* bias = dir ? bb : bf;
    int gbase = n0 & 1023;
    int tid = threadIdx.x;

    if (tid < 64) ws[tid] = sent[t*64 + tid];
    __syncthreads();

    float acc[4][4];
    #pragma unroll
    for (int i=0;i<4;i++)
        #pragma unroll
        for (int j=0;j<4;j++) acc[i][j] = 0.f;

    int tx = tid & 15;   // batch group (4 rows)
    int ty = tid >> 4;   // gate group  (4 cols)

    for (int kt = 0; kt < 10; kt++) {
        int k0 = kt * 32;
        #pragma unroll
        for (int i=0;i<8;i++) {
            int idx = tid + i*256;          // 0..2047
            int m  = idx >> 5;              // 0..63
            int kk = idx & 31;
            int kg = k0 + kk;
            float av = 0.f, bv = 0.f;
            if (kg < EMB) {
                av = emb[ws[m]*EMB + kg];
                bv = W[(gbase + m)*EMB + kg];
            }
            As[kk*68 + m] = av;
            Bs[kk*68 + m] = bv;
        }
        __syncthreads();
        #pragma unroll
        for (int kk=0; kk<32; kk++) {
            float4 a = *(const float4*)&As[kk*68 + tx*4];
            float4 b = *(const float4*)&Bs[kk*68 + ty*4];
            acc[0][0] += a.x*b.x; acc[0][1] += a.x*b.y; acc[0][2] += a.x*b.z; acc[0][3] += a.x*b.w;
            acc[1][0] += a.y*b.x; acc[1][1] += a.y*b.y; acc[1][2] += a.y*b.z; acc[1][3] += a.y*b.w;
            acc[2][0] += a.z*b.x; acc[2][1] += a.z*b.y; acc[2][2] += a.z*b.z; acc[2][3] += a.z*b.w;
            acc[3][0] += a.w*b.x; acc[3][1] += a.w*b.y; acc[3][2] += a.w*b.z; acc[3][3] += a.w*b.w;
        }
        __syncthreads();
    }

    #pragma unroll
    for (int j=0;j<4;j++) {
        int g = gbase + ty*4 + j;
        float bv = bias[g];
        float4 o = make_float4(acc[0][j]+bv, acc[1][j]+bv, acc[2][j]+bv, acc[3][j]+bv);
        *(float4*)&g_xproj[dir][t][g][tx*4] = o;
    }
}

// =============================================================================
// Kernel 2: persistent bidirectional LSTM. 128 CTAs (64 fwd + 64 bwd), 256 thr.
// CTA c owns h columns [4c,4c+4): computes gate cols {q*256+4c+j}, updates h/c
// locally, one grid barrier per step.
// =============================================================================
__device__ __forceinline__ float sigf(float x){ return 1.f/(1.f + __expf(-x)); }

__device__ __forceinline__ void grid_barrier(unsigned target)
{
    __syncthreads();
    if (threadIdx.x == 0) {
        __threadfence();
        unsigned a = atomicAdd(&g_bar[0], 1u);
        if (a == 127u) {
            g_bar[0] = 0u;
            __threadfence();
            atomicExch(&g_bar[1], target);
        } else {
            volatile unsigned* rel = &g_bar[1];
            while (*rel < target) { }
        }
        __threadfence();
    }
    __syncthreads();
}

__global__ void __launch_bounds__(256) k_lstm(
    const float* __restrict__ Whf, const float* __restrict__ Whb)
{
    extern __shared__ float sm[];
    float* Ws = sm;                 // [k=256][16]   (16KB)
    float* hs = sm + 4096;          // [k=256][b=64] (64KB)
    float* gb = sm + 4096 + 16384;  // [16][68]      (~4.3KB)

    int bx  = blockIdx.x;
    int dir = bx >> 6;
    int c   = bx & 63;
    const float* Whh = dir ? Whb : Whf;
    int tid = threadIdx.x;

    // preload Whh slice: Ws[k*16 + (q*4+j)] = Whh[q*256 + 4c + j][k]
    for (int idx = tid; idx < 4096; idx += 256) {
        int k = idx & 255, r = idx >> 8;   // r = q*4+j
        int q = r >> 2, j = r & 3;
        Ws[k*16 + r] = Whh[(q*256 + 4*c + j)*HID + k];
    }

    int gi = tid & 15;       // which of 16 gate cols (q*4+j)
    int bg = tid >> 4;       // batch group (4 each)
    int q  = gi >> 2, jj = gi & 3;
    int jrow = tid >> 6;     // update phase: hid col offset 0..3
    int bcol = tid & 63;     // update phase: batch
    float cstate = 0.f;

    float* hb = &g_h[dir][0][0][0];

    for (int step = 0; step < T; step++) {
        int t = dir ? (T-1-step) : step;
        if (step > 0) {
            int tprev = dir ? (t+1) : (t-1);
            const float4* hsrc = (const float4*)(hb + tprev*HID*Bt);
            for (int i = tid; i < 4096; i += 256)
                ((float4*)hs)[i] = hsrc[i];
        }
        __syncthreads();

        // prefetch this thread's x_proj contribution early
        float4 xp4 = *(const float4*)&g_xproj[dir][t][q*256 + 4*c + jj][bg*4];

        float a0=0.f, a1=0.f, a2=0.f, a3=0.f;
        if (step > 0) {
            #pragma unroll 8
            for (int k=0;k<HID;k++) {
                float  w  = Ws[k*16 + gi];
                float4 h4 = *(const float4*)&hs[k*64 + bg*4];
                a0 += w*h4.x; a1 += w*h4.y; a2 += w*h4.z; a3 += w*h4.w;
            }
        }
        *(float4*)&gb[gi*68 + bg*4] =
            make_float4(a0+xp4.x, a1+xp4.y, a2+xp4.z, a3+xp4.w);
        __syncthreads();

        // h/c update: thread -> (hid col 4c+jrow, batch bcol)
        float iv = gb[( 0 + jrow)*68 + bcol];
        float fv = gb[( 4 + jrow)*68 + bcol];
        float gv = gb[( 8 + jrow)*68 + bcol];
        float ov = gb[(12 + jrow)*68 + bcol];
        cstate = sigf(fv)*cstate + sigf(iv)*tanhf(gv);
        float hv = sigf(ov)*tanhf(cstate);
        hb[t*HID*Bt + (4*c + jrow)*Bt + bcol] = hv;

        grid_barrier((unsigned)(step+1));
    }
}

// =============================================================================
// Kernel 3: emissions[t][b][l] = concat(h_f,h_b)[t][b][:] . W_top[l][:] + b_top
// one CTA per t.
// =============================================================================
__global__ void __launch_bounds__(256) k_emis(
    const float* __restrict__ Wt, const float* __restrict__ bt)
{
    extern __shared__ float sm[];
    float* Wts = sm;            // 20*512
    float* hch = sm + 10240;    // 64x64 chunk

    int t = blockIdx.x, tid = threadIdx.x;
    for (int i = tid; i < NLAB*2*HID; i += 256) Wts[i] = Wt[i];

    float acc[5] = {0.f,0.f,0.f,0.f,0.f};
    int b = tid & 63;
    int lbase = tid >> 6;       // l = lbase + 4*s

    for (int d=0; d<2; d++) {
        const float* hsrc = &g_h[d][t][0][0];
        for (int jc=0; jc<4; jc++) {
            __syncthreads();
            for (int i = tid; i < 4096; i += 256) hch[i] = hsrc[jc*4096 + i];
            __syncthreads();
            #pragma unroll 4
            for (int j2=0;j2<64;j2++) {
                float hv = hch[j2*64 + b];
                #pragma unroll
                for (int s=0;s<5;s++) {
                    int l = lbase + 4*s;
                    acc[s] += hv * Wts[l*2*HID + d*HID + jc*64 + j2];
                }
            }
        }
    }
    #pragma unroll
    for (int s=0;s<5;s++) {
        int l = lbase + 4*s;
        g_em[t][b][l] = acc[s] + bt[l];
    }
}

// =============================================================================
// Kernel 4: CRF per batch. warp0: alpha recursion (lane=j). warp1: gold score.
// =============================================================================
__global__ void __launch_bounds__(64) k_crf(
    const int* __restrict__ sent, const int* __restrict__ labels,
    const float* __restrict__ start_t, const float* __restrict__ end_t,
    const float* __restrict__ trans)
{
    int b = blockIdx.x;
    int tid = threadIdx.x;
    __shared__ float s_score, s_denom;

    if (tid < 32) {
        int j = tid;
        float tcol[NLAB];
        #pragma unroll
        for (int i=0;i<NLAB;i++) tcol[i] = (j < NLAB) ? trans[i*NLAB + j] : 0.f;
        float alpha = (j < NLAB) ? (start_t[j] + g_em[0][b][j]) : -1e30f;

        for (int t=1; t<T; t++) {
            bool m = (sent[t*64 + b] != 0);
            float em = (j < NLAB) ? g_em[t][b][j] : 0.f;
            float s[NLAB], mx = -1e30f;
            #pragma unroll
            for (int i=0;i<NLAB;i++) {
                float ai = __shfl_sync(0xffffffffu, alpha, i);
                s[i] = ai + tcol[i];
                mx = fmaxf(mx, s[i]);
            }
            float sum = 0.f;
            #pragma unroll
            for (int i=0;i<NLAB;i++) sum += __expf(s[i] - mx);
            float nxt = em + mx + __logf(sum);
            if (j < NLAB && m) alpha = nxt;
        }
        float v = (j < NLAB) ? (alpha + end_t[j]) : -1e30f;
        float mx = v;
        #pragma unroll
        for (int o=16;o>0;o>>=1) mx = fmaxf(mx, __shfl_xor_sync(0xffffffffu, mx, o));
        float e = (j < NLAB) ? __expf(v - mx) : 0.f;
        #pragma unroll
        for (int o=16;o>0;o>>=1) e += __shfl_xor_sync(0xffffffffu, e, o);
        if (tid == 0) s_denom = mx + __logf(e);
    } else {
        int l = tid - 32;
        float part = 0.f; int cnt = 0;
        for (int t = l; t < T; t += 32) {
            bool m = (sent[t*64 + b] != 0);
            cnt += m ? 1 : 0;
            if (t >= 1 && m) {
                int tp = labels[(t-1)*64 + b];
                int tc = labels[t*64 + b];
                part += trans[tp*NLAB + tc] + g_em[t][b][tc];
            }
        }
        #pragma unroll
        for (int o=16;o>0;o>>=1) {
            part += __shfl_xor_sync(0xffffffffu, part, o);
            cnt  += __shfl_xor_sync(0xffffffffu, cnt, o);
        }
        if (l == 0) {
            int tag0 = labels[b];
            float score = start_t[tag0] + g_em[0][b][tag0] + part;
            int se = cnt - 1;
            int last = labels[se*64 + b];
            score += end_t[last];
            s_score = score;
        }
    }
    __syncthreads();
    if (tid == 0) g_part[b] = s_denom - s_score;   // contributes -(score - denom)
}

// Deterministic final reduce (fixed order, no atomics)
__global__ void k_reduce(float* out)
{
    if (threadIdx.x == 0) {
        float s = 0.f;
        for (int b=0;b<Bt;b++) s += g_part[b];
        out[0] = s;
    }
}

// =============================================================================
extern "C" void kernel_launch(void* const* d_in, const int* in_sizes, int n_in,
                              void* d_out, int out_size)
{
    const float* emb    = (const float*)d_in[0];
    const float* Wih_f  = (const float*)d_in[1];
    const float* Whh_f  = (const float*)d_in[2];
    const float* b_f    = (const float*)d_in[3];
    const float* Wih_b  = (const float*)d_in[4];
    const float* Whh_b  = (const float*)d_in[5];
    const float* b_b    = (const float*)d_in[6];
    const float* W_top  = (const float*)d_in[7];
    const float* b_top  = (const float*)d_in[8];
    const float* startt = (const float*)d_in[9];
    const float* endt   = (const float*)d_in[10];
    const float* trans  = (const float*)d_in[11];
    const int*   sent   = (const int*)d_in[12];
    const int*   labels = (const int*)d_in[13];
    float* out = (float*)d_out;

    cudaFuncSetAttribute(k_lstm, cudaFuncAttributeMaxDynamicSharedMemorySize, 86272);
    cudaFuncSetAttribute(k_emis, cudaFuncAttributeMaxDynamicSharedMemorySize, 57344);

    // reset software grid barrier (graph-capturable async memset)
    void* barp = nullptr;
    cudaGetSymbolAddress(&barp, g_bar);
    cudaMemsetAsync(barp, 0, 2*sizeof(unsigned));

    k_xproj<<<dim3(32, 256), 256>>>(emb, Wih_f, b_f, Wih_b, b_b, sent);
    k_lstm <<<128, 256, 86272>>>(Whh_f, Whh_b);
    k_emis <<<256, 256, 57344>>>(W_top, b_top);
    k_crf  <<<64, 64>>>(sent, labels, startt, endt, trans);
    k_reduce<<<1, 32>>>(out);
}